// round 2
// baseline (speedup 1.0000x reference)
#include <cuda_runtime.h>

#define BB 256
#define SS 2048
#define VOCAB 10
#define EE 32
#define HH 64
#define OUTD 10
#define HSTRIDE 68   // 68*4 = 272 bytes, multiple of 16 -> 16B-aligned rows

// ---- packed f32x2 helpers (sm_103a) ----
__device__ __forceinline__ unsigned long long pk2(float lo, float hi) {
    unsigned long long r;
    asm("mov.b64 %0, {%1, %2};" : "=l"(r) : "f"(lo), "f"(hi));
    return r;
}
__device__ __forceinline__ void fma2(unsigned long long& acc,
                                     unsigned long long a, unsigned long long b) {
    asm("fma.rn.f32x2 %0, %1, %2, %0;" : "+l"(acc) : "l"(a), "l"(b));
}
__device__ __forceinline__ unsigned long long add2(unsigned long long a,
                                                   unsigned long long b) {
    unsigned long long r;
    asm("add.rn.f32x2 %0, %1, %2;" : "=l"(r) : "l"(a), "l"(b));
    return r;
}
__device__ __forceinline__ float2 unpk2(unsigned long long x) {
    float lo, hi;
    asm("mov.b64 {%0, %1}, %2;" : "=f"(lo), "=f"(hi) : "l"(x));
    return make_float2(lo, hi);
}
// tanh = 1 - 2/(exp(2z)+1), via MUFU EX2 + RCP (rel err ~1e-7)
__device__ __forceinline__ float fast_tanh(float z) {
    float t = z * 2.885390081777927f;  // 2*log2(e)
    float e; asm("ex2.approx.f32 %0, %1;" : "=f"(e) : "f"(t));
    float r; asm("rcp.approx.f32 %0, %1;" : "=f"(r) : "f"(e + 1.0f));
    return fmaf(-2.0f, r, 1.0f);
}

__global__ __launch_bounds__(64) void rnn_fused2_kernel(
    const int* __restrict__ num1, const int* __restrict__ num2,
    const float* __restrict__ embed, const float* __restrict__ Wx,
    const float* __restrict__ Wh, const float* __restrict__ b,
    const float* __restrict__ Wd, const float* __restrict__ bd,
    float* __restrict__ out)
{
    __shared__ float t1[VOCAB][HH];
    __shared__ float t2[VOCAB][HH];
    __shared__ unsigned char idx[2][SS];                 // nibble-packed (n1 | n2<<4)
    __shared__ __align__(16) float hist[2][64][HSTRIDE]; // rotating h history per row
    __shared__ __align__(16) unsigned long long wd2[OUTD][HH / 2]; // packed Wd columns
    __shared__ float bd_sh[OUTD];

    const int j  = threadIdx.x;          // 0..63, owns h[j] for both rows
    const int r0 = blockIdx.x * 2;       // this block's two batch rows

    // ---- Prologue: input-projection tables (only 10+10 distinct halves) ----
    {
        float wxa[EE], wxb[EE];
        #pragma unroll
        for (int e = 0; e < EE; e++) {
            wxa[e] = Wx[e * HH + j];
            wxb[e] = Wx[(EE + e) * HH + j];
        }
        float bj = b[j];
        #pragma unroll
        for (int v = 0; v < VOCAB; v++) {
            float a1 = bj, a2 = 0.0f;
            #pragma unroll
            for (int e = 0; e < EE; e++) {
                float ev = embed[v * EE + e];
                a1 = fmaf(ev, wxa[e], a1);
                a2 = fmaf(ev, wxb[e], a2);
            }
            t1[v][j] = a1;
            t2[v][j] = a2;
        }
    }

    // ---- Wh column j as 32 packed pairs ----
    unsigned long long wpk[HH / 2];
    #pragma unroll
    for (int k = 0; k < HH / 2; k++)
        wpk[k] = pk2(Wh[(2 * k) * HH + j], Wh[(2 * k + 1) * HH + j]);

    // ---- Token indices, nibble-packed, both rows ----
    {
        const int* n1A = num1 + (size_t)r0 * SS;
        const int* n2A = num2 + (size_t)r0 * SS;
        const int* n1B = n1A + SS;
        const int* n2B = n2A + SS;
        for (int i = j; i < SS; i += HH) {
            idx[0][i] = (unsigned char)(n1A[i] | (n2A[i] << 4));
            idx[1][i] = (unsigned char)(n1B[i] | (n2B[i] << 4));
        }
    }

    // ---- Output weights: packed over k pairs, bias ----
    for (int i = j; i < OUTD * (HH / 2); i += HH) {
        int o = i >> 5, k2 = i & 31;
        wd2[o][k2] = pk2(Wd[(2 * k2) * OUTD + o], Wd[(2 * k2 + 1) * OUTD + o]);
    }
    if (j < OUTD) bd_sh[j] = bd[j];

    hist[0][63][j] = 0.0f;   // h_{-1} = 0 (step s reads slot (s+63)&63)
    hist[1][63][j] = 0.0f;
    __syncthreads();

    float* outA = out + (size_t)r0 * SS * OUTD;
    float* outB = outA + (size_t)SS * OUTD;

    for (int s = 0; s < SS; s++) {
        const int ia = idx[0][s];
        const int ib = idx[1][s];
        unsigned long long aA[4], aB[4];
        aA[0] = pk2(t1[ia & 15][j] + t2[ia >> 4][j], 0.0f);
        aB[0] = pk2(t1[ib & 15][j] + t2[ib >> 4][j], 0.0f);
        aA[1] = aA[2] = aA[3] = 0ull;
        aB[1] = aB[2] = aB[3] = 0ull;

        const ulonglong2* ha = (const ulonglong2*)hist[0][(s + 63) & 63];
        const ulonglong2* hb = (const ulonglong2*)hist[1][(s + 63) & 63];
        #pragma unroll
        for (int k = 0; k < 16; k++) {     // 16B broadcast loads, 2 packed pairs each
            ulonglong2 hA = ha[k];
            fma2(aA[(2 * k) & 3],     hA.x, wpk[2 * k]);
            fma2(aA[(2 * k + 1) & 3], hA.y, wpk[2 * k + 1]);
            ulonglong2 hB = hb[k];
            fma2(aB[(2 * k) & 3],     hB.x, wpk[2 * k]);
            fma2(aB[(2 * k + 1) & 3], hB.y, wpk[2 * k + 1]);
        }
        float2 uA = unpk2(add2(add2(aA[0], aA[1]), add2(aA[2], aA[3])));
        float2 uB = unpk2(add2(add2(aB[0], aB[1]), add2(aB[2], aB[3])));
        float hAn = fast_tanh(uA.x + uA.y);
        float hBn = fast_tanh(uB.x + uB.y);
        hist[0][s & 63][j] = hAn;
        hist[1][s & 63][j] = hBn;
        __syncthreads();    // h_s visible before step s+1 (covers both rows)

        if ((s & 63) == 63) {
            // ---- Fused output projection: thread j = local step j, both rows ----
            const int s0 = s - 63;
            #pragma unroll
            for (int r = 0; r < 2; r++) {
                const unsigned long long* hp =
                    (const unsigned long long*)hist[r][j];
                unsigned long long oacc[OUTD];
                #pragma unroll
                for (int o = 0; o < OUTD; o++) oacc[o] = 0ull;
                #pragma unroll
                for (int k2 = 0; k2 < HH / 2; k2++) {
                    unsigned long long hv = hp[k2];
                    #pragma unroll
                    for (int o = 0; o < OUTD; o++) fma2(oacc[o], hv, wd2[o][k2]);
                }
                float res[OUTD];
                #pragma unroll
                for (int o = 0; o < OUTD; o++) {
                    float2 u = unpk2(oacc[o]);
                    res[o] = u.x + u.y + bd_sh[o];
                }
                float* op = (r == 0 ? outA : outB) + (size_t)(s0 + j) * OUTD;
                float2* op2 = (float2*)op;   // 40B-offset rows -> 8B aligned
                #pragma unroll
                for (int o = 0; o < OUTD / 2; o++)
                    op2[o] = make_float2(res[2 * o], res[2 * o + 1]);
            }
            __syncthreads();  // epilogue reads done before slot 0 is overwritten
        }
    }
}

extern "C" void kernel_launch(void* const* d_in, const int* in_sizes, int n_in,
                              void* d_out, int out_size)
{
    (void)in_sizes; (void)n_in; (void)out_size;
    const int*   num1  = (const int*)d_in[0];
    const int*   num2  = (const int*)d_in[1];
    const float* embed = (const float*)d_in[2];
    const float* Wx    = (const float*)d_in[3];
    const float* Wh    = (const float*)d_in[4];
    const float* b     = (const float*)d_in[5];
    const float* Wd    = (const float*)d_in[6];
    const float* bd    = (const float*)d_in[7];
    float* out = (float*)d_out;

    rnn_fused2_kernel<<<BB / 2, HH>>>(num1, num2, embed, Wx, Wh, b, Wd, bd, out);
}

// round 3
// speedup vs baseline: 1.2508x; 1.2508x over previous
#include <cuda_runtime.h>

#define BB 256
#define SS 2048
#define VOCAB 10
#define EE 32
#define HH 64
#define OUTD 10
#define HSTRIDE 68   // 68*4 = 272 bytes, multiple of 16 -> 16B-aligned rows

typedef unsigned long long ull;

// ---- packed f32x2 helpers (sm_103a) ----
__device__ __forceinline__ ull pk2(float lo, float hi) {
    ull r;
    asm("mov.b64 %0, {%1, %2};" : "=l"(r) : "f"(lo), "f"(hi));
    return r;
}
__device__ __forceinline__ void fma2(ull& acc, ull a, ull b) {
    asm("fma.rn.f32x2 %0, %1, %2, %0;" : "+l"(acc) : "l"(a), "l"(b));
}
__device__ __forceinline__ ull add2(ull a, ull b) {
    ull r;
    asm("add.rn.f32x2 %0, %1, %2;" : "=l"(r) : "l"(a), "l"(b));
    return r;
}
__device__ __forceinline__ float2 unpk2(ull x) {
    float lo, hi;
    asm("mov.b64 {%0, %1}, %2;" : "=f"(lo), "=f"(hi) : "l"(x));
    return make_float2(lo, hi);
}
// tanh = 1 - 2/(exp(2z)+1) via EX2 + RCP (rel err ~1e-7)
__device__ __forceinline__ float fast_tanh(float z) {
    float t = z * 2.885390081777927f;  // 2*log2(e)
    float e; asm("ex2.approx.f32 %0, %1;" : "=f"(e) : "f"(t));
    float r; asm("rcp.approx.f32 %0, %1;" : "=f"(r) : "f"(e + 1.0f));
    return fmaf(-2.0f, r, 1.0f);
}

__global__ __launch_bounds__(256) void rnn_split_kernel(
    const int* __restrict__ num1, const int* __restrict__ num2,
    const float* __restrict__ embed, const float* __restrict__ Wx,
    const float* __restrict__ Wh, const float* __restrict__ b,
    const float* __restrict__ Wd, const float* __restrict__ bd,
    float* __restrict__ out)
{
    __shared__ float t1[VOCAB][HH];
    __shared__ float t2[VOCAB][HH];
    __shared__ unsigned char idx[2][SS];                  // nibble-packed tokens
    __shared__ __align__(16) float hist[2][64][HSTRIDE];  // rotating h history
    __shared__ float wd_sh[HH][OUTD];
    __shared__ float bd_sh[OUTD];

    const int tid  = threadIdx.x;     // 0..255
    const int rowL = tid >> 7;        // warps 0-3 -> row A, warps 4-7 -> row B
    const int t    = tid & 127;
    const int j    = t >> 1;          // hidden unit owned by this thread pair
    const int half = t & 1;           // which 32-k half of the dot product
    const int kb   = 32 * half;
    const int r0   = blockIdx.x * 2;

    // ---- Prologue: input-projection tables (only 10+10 distinct halves) ----
    if (tid < HH) {
        const int jj = tid;
        float wxa[EE], wxb[EE];
        #pragma unroll
        for (int e = 0; e < EE; e++) {
            wxa[e] = Wx[e * HH + jj];
            wxb[e] = Wx[(EE + e) * HH + jj];
        }
        float bj = b[jj];
        #pragma unroll
        for (int v = 0; v < VOCAB; v++) {
            float a1 = bj, a2 = 0.0f;
            #pragma unroll
            for (int e = 0; e < EE; e++) {
                float ev = embed[v * EE + e];
                a1 = fmaf(ev, wxa[e], a1);
                a2 = fmaf(ev, wxb[e], a2);
            }
            t1[v][jj] = a1;
            t2[v][jj] = a2;
        }
    }

    // ---- Output weights + bias ----
    for (int i = tid; i < HH * OUTD; i += 256) wd_sh[i / OUTD][i % OUTD] = Wd[i];
    if (tid < OUTD) bd_sh[tid] = bd[tid];

    // ---- Token indices, nibble-packed, both rows ----
    {
        const int* n1A = num1 + (size_t)r0 * SS;
        const int* n2A = num2 + (size_t)r0 * SS;
        for (int i = tid; i < SS; i += 256) {
            idx[0][i] = (unsigned char)(n1A[i] | (n2A[i] << 4));
            idx[1][i] = (unsigned char)(n1A[SS + i] | (n2A[SS + i] << 4));
        }
    }

    // ---- This thread's 16 packed Wh pairs: k in [kb, kb+32), column j ----
    ull wpk[16];
    #pragma unroll
    for (int m = 0; m < 16; m++)
        wpk[m] = pk2(Wh[(kb + 2 * m) * HH + j], Wh[(kb + 2 * m + 1) * HH + j]);

    if (half == 0) hist[rowL][63][j] = 0.0f;   // h_{-1} = 0
    __syncthreads();

    float* outrow = out + (size_t)(r0 + rowL) * SS * OUTD;

    for (int s = 0; s < SS; s++) {
        const int pk = idx[rowL][s];
        // off critical path: the FMA chain below runs in parallel with these
        float t12 = (half == 0) ? (t1[pk & 15][j] + t2[pk >> 4][j]) : 0.0f;

        const ulonglong2* hv =
            (const ulonglong2*)(hist[rowL][(s + 63) & 63] + kb);
        ull a0 = 0ull, a1 = 0ull;
        #pragma unroll
        for (int m = 0; m < 8; m++) {   // 16B broadcast loads, 2 packed pairs each
            ulonglong2 hh = hv[m];
            fma2(a0, hh.x, wpk[2 * m]);
            fma2(a1, hh.y, wpk[2 * m + 1]);
        }
        float2 u = unpk2(add2(a0, a1));
        float partial = u.x + u.y + t12;
        partial += __shfl_xor_sync(0xFFFFFFFFu, partial, 1);  // combine halves
        float hn = fast_tanh(partial);
        if (half == 0) hist[rowL][s & 63][j] = hn;
        __syncthreads();   // h_s visible to all before step s+1

        if ((s & 63) == 63) {
            // ---- Fused output projection: thread (step=t>>1, half of OUTD) ----
            const int step = t >> 1;
            const int ob   = 5 * half;
            const float* hr = hist[rowL][step];
            float oa[5];
            #pragma unroll
            for (int o = 0; o < 5; o++) oa[o] = bd_sh[ob + o];
            #pragma unroll 8
            for (int k = 0; k < HH; k++) {
                float hvv = hr[k];
                #pragma unroll
                for (int o = 0; o < 5; o++)
                    oa[o] = fmaf(hvv, wd_sh[k][ob + o], oa[o]);
            }
            float* op = outrow + (size_t)(s - 63 + step) * OUTD + ob;
            #pragma unroll
            for (int o = 0; o < 5; o++) op[o] = oa[o];
            __syncthreads();   // epilogue reads done before slot 0 overwritten
        }
    }
}

extern "C" void kernel_launch(void* const* d_in, const int* in_sizes, int n_in,
                              void* d_out, int out_size)
{
    (void)in_sizes; (void)n_in; (void)out_size;
    const int*   num1  = (const int*)d_in[0];
    const int*   num2  = (const int*)d_in[1];
    const float* embed = (const float*)d_in[2];
    const float* Wx    = (const float*)d_in[3];
    const float* Wh    = (const float*)d_in[4];
    const float* b     = (const float*)d_in[5];
    const float* Wd    = (const float*)d_in[6];
    const float* bd    = (const float*)d_in[7];
    float* out = (float*)d_out;

    rnn_split_kernel<<<BB / 2, 256>>>(num1, num2, embed, Wx, Wh, b, Wd, bd, out);
}

// round 4
// speedup vs baseline: 2.3157x; 1.8513x over previous
#include <cuda_runtime.h>

#define BB 256
#define SS 2048
#define VOCAB 10
#define EE 32
#define HH 64
#define OUTD 10
#define HSTRIDE 68   // 272B rows: 16B-aligned, spreads banks for epilogue

typedef unsigned long long ull;

// ---- packed f32x2 helpers (sm_103a) ----
__device__ __forceinline__ ull pk2(float lo, float hi) {
    ull r;
    asm("mov.b64 %0, {%1, %2};" : "=l"(r) : "f"(lo), "f"(hi));
    return r;
}
__device__ __forceinline__ void fma2(ull& acc, ull a, ull b) {
    asm("fma.rn.f32x2 %0, %1, %2, %0;" : "+l"(acc) : "l"(a), "l"(b));
}
__device__ __forceinline__ ull add2(ull a, ull b) {
    ull r;
    asm("add.rn.f32x2 %0, %1, %2;" : "=l"(r) : "l"(a), "l"(b));
    return r;
}
__device__ __forceinline__ float2 unpk2(ull x) {
    float lo, hi;
    asm("mov.b64 {%0, %1}, %2;" : "=f"(lo), "=f"(hi) : "l"(x));
    return make_float2(lo, hi);
}
// tanh = 1 - 2/(exp(2z)+1) via EX2 + RCP (rel err ~1e-7)
__device__ __forceinline__ float fast_tanh(float z) {
    float t = z * 2.885390081777927f;  // 2*log2(e)
    float e; asm("ex2.approx.f32 %0, %1;" : "=f"(e) : "f"(t));
    float r; asm("rcp.approx.f32 %0, %1;" : "=f"(r) : "f"(e + 1.0f));
    return fmaf(-2.0f, r, 1.0f);
}
__device__ __forceinline__ void rowbar(int id) {
    asm volatile("bar.sync %0, 64;" :: "r"(id) : "memory");
}

__global__ __launch_bounds__(128, 1) void rnn_group_kernel(
    const int* __restrict__ num1, const int* __restrict__ num2,
    const float* __restrict__ embed, const float* __restrict__ Wx,
    const float* __restrict__ Wh, const float* __restrict__ b,
    const float* __restrict__ Wd, const float* __restrict__ bd,
    float* __restrict__ out)
{
    __shared__ float t1f[VOCAB][HH];                       // input-proj tables
    __shared__ float t2f[VOCAB][HH];
    __shared__ unsigned char idx[2][SS];                   // nibble-packed tokens
    __shared__ __align__(16) float hist[2][64][HSTRIDE];   // rotating h history
    __shared__ __align__(8)  float wdkT[OUTD][HH];         // Wd transposed [o][k]
    __shared__ float bd_sh[OUTD];

    const int tid  = threadIdx.x;     // 0..127
    const int rowL = tid >> 6;        // warps 0,1 -> row A ; warps 2,3 -> row B
    const int c    = tid & 63;        // hidden column owned by this thread
    const int barid = 1 + rowL;       // named barrier per row-group
    const int r0   = blockIdx.x * 2;

    // ---- Prologue ----
    if (tid < HH) {   // input-projection tables (10+10 distinct halves)
        const int jj = tid;
        float wxa[EE], wxb[EE];
        #pragma unroll
        for (int e = 0; e < EE; e++) {
            wxa[e] = Wx[e * HH + jj];
            wxb[e] = Wx[(EE + e) * HH + jj];
        }
        float bj = b[jj];
        #pragma unroll
        for (int v = 0; v < VOCAB; v++) {
            float a1 = bj, a2 = 0.0f;
            #pragma unroll
            for (int e = 0; e < EE; e++) {
                float ev = embed[v * EE + e];
                a1 = fmaf(ev, wxa[e], a1);
                a2 = fmaf(ev, wxb[e], a2);
            }
            t1f[v][jj] = a1;
            t2f[v][jj] = a2;
        }
    }
    // Wd transposed + bias
    for (int i = tid; i < HH * OUTD; i += 128) wdkT[i % OUTD][i / OUTD] = Wd[i];
    if (tid < OUTD) bd_sh[tid] = bd[tid];
    // token indices, nibble-packed, both rows
    {
        const int* n1A = num1 + (size_t)r0 * SS;
        const int* n2A = num2 + (size_t)r0 * SS;
        for (int i = tid; i < SS; i += 128) {
            idx[0][i] = (unsigned char)(n1A[i] | (n2A[i] << 4));
            idx[1][i] = (unsigned char)(n1A[SS + i] | (n2A[SS + i] << 4));
        }
    }
    // Wh column c as 32 packed k-pairs (coalesced across threads)
    ull w[HH / 2];
    #pragma unroll
    for (int m = 0; m < HH / 2; m++)
        w[m] = pk2(Wh[(2 * m) * HH + c], Wh[(2 * m + 1) * HH + c]);

    hist[rowL][63][c] = 0.0f;   // h_{-1} = 0 (step s reads slot (s+63)&63)
    __syncthreads();

    float* outrow = out + (size_t)(r0 + rowL) * SS * OUTD;

    for (int s = 0; s < SS; s++) {
        const int pkb = idx[rowL][s];
        const float t12 = t1f[pkb & 15][c] + t2f[pkb >> 4][c];  // off critical path

        const ulonglong2* hv = (const ulonglong2*)hist[rowL][(s + 63) & 63];
        ull a0 = 0ull, a1 = 0ull, a2 = 0ull, a3 = 0ull;
        #pragma unroll
        for (int m = 0; m < 8; m++) {   // 16B broadcast loads; 32 FMA2 total
            ulonglong2 hh0 = hv[2 * m];
            fma2(a0, hh0.x, w[4 * m + 0]);
            fma2(a1, hh0.y, w[4 * m + 1]);
            ulonglong2 hh1 = hv[2 * m + 1];
            fma2(a2, hh1.x, w[4 * m + 2]);
            fma2(a3, hh1.y, w[4 * m + 3]);
        }
        float2 u = unpk2(add2(add2(a0, a1), add2(a2, a3)));
        float hn = fast_tanh(u.x + u.y + t12);
        hist[rowL][s & 63][c] = hn;       // conflict-free: bank = c%32
        rowbar(barid);                    // h_s visible to the row-group

        if ((s & 63) == 63) {
            // ---- Fused output projection: thread c handles local step c ----
            const ull* hp = (const ull*)hist[rowL][c];
            ull oacc[OUTD];
            #pragma unroll
            for (int o = 0; o < OUTD; o++) oacc[o] = 0ull;
            #pragma unroll
            for (int k2 = 0; k2 < HH / 2; k2++) {
                ull hvv = hp[k2];
                const ull* wdp = (const ull*)wdkT[0];
                #pragma unroll
                for (int o = 0; o < OUTD; o++)
                    fma2(oacc[o], hvv, *((const ull*)wdkT[o] + k2));
            }
            float* op = outrow + (size_t)(s - 63 + c) * OUTD;
            float2* op2 = (float2*)op;    // 40B rows -> 8B aligned
            #pragma unroll
            for (int o = 0; o < OUTD / 2; o++) {
                float2 ua = unpk2(oacc[2 * o]);
                float2 ub = unpk2(oacc[2 * o + 1]);
                op2[o] = make_float2(ua.x + ua.y + bd_sh[2 * o],
                                     ub.x + ub.y + bd_sh[2 * o + 1]);
            }
            rowbar(barid);   // epilogue reads done before slots are overwritten
        }
    }
}

extern "C" void kernel_launch(void* const* d_in, const int* in_sizes, int n_in,
                              void* d_out, int out_size)
{
    (void)in_sizes; (void)n_in; (void)out_size;
    const int*   num1  = (const int*)d_in[0];
    const int*   num2  = (const int*)d_in[1];
    const float* embed = (const float*)d_in[2];
    const float* Wx    = (const float*)d_in[3];
    const float* Wh    = (const float*)d_in[4];
    const float* b     = (const float*)d_in[5];
    const float* Wd    = (const float*)d_in[6];
    const float* bd    = (const float*)d_in[7];
    float* out = (float*)d_out;

    rnn_group_kernel<<<BB / 2, 128>>>(num1, num2, embed, Wx, Wh, b, Wd, bd, out);
}